// round 12
// baseline (speedup 1.0000x reference)
#include <cuda_runtime.h>
#include <cuda_fp16.h>
#include <cstdint>
#include <cstddef>

#define NB 4
#define SEQ 2048
#define NH 16
#define HD 64
#define DMODEL 1024

// Scratch (allocation-free rule -> __device__ globals), all fp16
__device__ __half g_x[3u * 8192u * 1024u];   // rounded inputs
__device__ __half g_wt[3u * 1024u * 1024u];  // W transposed [n][k]
__device__ __half g_q[NB * SEQ * DMODEL];    // Q pre-scaled by 0.125
__device__ __half g_k[NB * SEQ * DMODEL];
__device__ __half g_v[NB * SEQ * DMODEL];

// ---------------------------------------------------------------------------
__device__ __forceinline__ uint32_t s2u(const void* p) {
    return (uint32_t)__cvta_generic_to_shared(p);
}
__device__ __forceinline__ void ldsm4(uint32_t& r0, uint32_t& r1, uint32_t& r2, uint32_t& r3,
                                      uint32_t addr) {
    asm volatile("ldmatrix.sync.aligned.m8n8.x4.shared.b16 {%0,%1,%2,%3}, [%4];"
                 : "=r"(r0), "=r"(r1), "=r"(r2), "=r"(r3) : "r"(addr));
}
__device__ __forceinline__ void ldsm4t(uint32_t& r0, uint32_t& r1, uint32_t& r2, uint32_t& r3,
                                       uint32_t addr) {
    asm volatile("ldmatrix.sync.aligned.m8n8.x4.trans.shared.b16 {%0,%1,%2,%3}, [%4];"
                 : "=r"(r0), "=r"(r1), "=r"(r2), "=r"(r3) : "r"(addr));
}
__device__ __forceinline__ void cpa16(uint32_t dst, const void* src) {
    asm volatile("cp.async.cg.shared.global [%0], [%1], 16;" :: "r"(dst), "l"(src));
}
__device__ __forceinline__ void cpa_commit() { asm volatile("cp.async.commit_group;"); }
template <int N> __device__ __forceinline__ void cpa_wait() {
    asm volatile("cp.async.wait_group %0;" :: "n"(N));
}
// pack two fp32 -> one f16x2 register (round-to-nearest-even, == __float2half_rn x2)
__device__ __forceinline__ uint32_t pack_f16x2(float lo, float hi) {
    uint32_t r;
    asm("cvt.rn.f16x2.f32 %0, %1, %2;" : "=r"(r) : "f"(hi), "f"(lo));
    return r;
}
// fp16 inputs, fp32 accumulate: same significand width as tf32, 2x rate, K=16
__device__ __forceinline__ void mma_f16(float c[4], const uint32_t a[4], uint32_t b0, uint32_t b1) {
    asm volatile(
        "mma.sync.aligned.m16n8k16.row.col.f32.f16.f16.f32 "
        "{%0,%1,%2,%3}, {%4,%5,%6,%7}, {%8,%9}, {%0,%1,%2,%3};\n"
        : "+f"(c[0]), "+f"(c[1]), "+f"(c[2]), "+f"(c[3])
        : "r"(a[0]), "r"(a[1]), "r"(a[2]), "r"(a[3]), "r"(b0), "r"(b1));
}

// ============================================================================
// prep 1: round X inputs to fp16
// ============================================================================
__global__ void round_x_kernel(const float4* __restrict__ xq,
                               const float4* __restrict__ xk,
                               const float4* __restrict__ xv) {
    const int z = blockIdx.y;
    const float4* src = (z == 0) ? xq : (z == 1) ? xk : xv;
    __half2* dst = (__half2*)(g_x + (size_t)z * 8388608u);
    size_t i = (size_t)blockIdx.x * blockDim.x + threadIdx.x;
    float4 v = src[i];
    dst[2 * i]     = __floats2half2_rn(v.x, v.y);
    dst[2 * i + 1] = __floats2half2_rn(v.z, v.w);
}

// ============================================================================
// prep 2: transpose + round W -> g_wt[z][n][k] fp16
// ============================================================================
__global__ void wtrans_kernel(const float* __restrict__ Wq,
                              const float* __restrict__ Wk,
                              const float* __restrict__ Wv) {
    __shared__ float smw[64][68];
    const int z = blockIdx.z;
    const float* W = (z == 0) ? Wq : (z == 1) ? Wk : Wv;
    __half* Wt = g_wt + (size_t)z * 1048576u;
    const int k0 = blockIdx.y * 64, n0 = blockIdx.x * 64;
    const int tid = threadIdx.x;
    #pragma unroll
    for (int i = 0; i < 4; i++) {
        int idx = tid + i * 256, r = idx >> 4, c4 = idx & 15;
        float4 v = *(const float4*)(W + (size_t)(k0 + r) * 1024 + n0 + c4 * 4);
        *(float4*)&smw[r][c4 * 4] = v;
    }
    __syncthreads();
    #pragma unroll
    for (int i = 0; i < 4; i++) {
        int idx = tid + i * 256, n = idx >> 4, c4 = idx & 15;
        __half* o = Wt + (size_t)(n0 + n) * 1024 + k0 + c4 * 4;
        *(__half2*)(o)     = __floats2half2_rn(smw[c4 * 4 + 0][n], smw[c4 * 4 + 1][n]);
        *(__half2*)(o + 2) = __floats2half2_rn(smw[c4 * 4 + 2][n], smw[c4 * 4 + 3][n]);
    }
}

// ============================================================================
// projections: X(fp16) @ W(fp16) + b, fp32 accum, out fp16.
// Block 128x128, BK=32, cp.async double-buffered, 256 threads (4m x 2n warps).
// ============================================================================
#define PSTR 40
__global__ __launch_bounds__(256, 2) void proj_kernel(
    const float* __restrict__ bq, const float* __restrict__ bk, const float* __restrict__ bv) {
    __shared__ __half As[2][128 * PSTR];
    __shared__ __half Bs[2][128 * PSTR];

    const int z = blockIdx.z;
    const __half* X  = g_x  + (size_t)z * 8388608u;
    const __half* Wt = g_wt + (size_t)z * 1048576u;
    const float* bias = (z == 0) ? bq : (z == 1) ? bk : bv;
    __half* out = (z == 0) ? g_q : (z == 1) ? g_k : g_v;
    const float scl = (z == 0) ? 0.125f : 1.0f;

    const int m0 = blockIdx.y * 128, n0 = blockIdx.x * 128;
    const int tid = threadIdx.x, warp = tid >> 5, lane = tid & 31;
    const int wm = warp >> 1, wn = warp & 1;
    const int gi = lane >> 2, tg = lane & 3;
    const int mi = lane >> 3, r8 = lane & 7;
    const uint32_t aoff2 = (((mi & 1) * 8 + r8) * PSTR + (mi >> 1) * 8) * 2;
    const uint32_t koff2 = (((mi >> 1) * 8 + r8) * PSTR + (mi & 1) * 8) * 2;
    const uint32_t Aa[2] = { s2u(As[0]), s2u(As[1]) };
    const uint32_t Ba[2] = { s2u(Bs[0]), s2u(Bs[1]) };

    auto issue = [&](int s, int kk) {
        #pragma unroll
        for (int i = 0; i < 2; i++) {
            int idx = tid + i * 256, r = idx >> 2, c8 = idx & 3;
            cpa16(Aa[s] + r * (PSTR * 2) + c8 * 16, X + (size_t)(m0 + r) * 1024 + kk + c8 * 8);
        }
        #pragma unroll
        for (int i = 0; i < 2; i++) {
            int idx = tid + i * 256, n = idx >> 2, c8 = idx & 3;
            cpa16(Ba[s] + n * (PSTR * 2) + c8 * 16, Wt + (size_t)(n0 + n) * 1024 + kk + c8 * 8);
        }
        cpa_commit();
    };

    float acc[2][8][4];
    #pragma unroll
    for (int i = 0; i < 2; i++)
        #pragma unroll
        for (int j = 0; j < 8; j++)
            #pragma unroll
            for (int c = 0; c < 4; c++) acc[i][j][c] = 0.f;

    issue(0, 0);
    for (int t = 0; t < 32; t++) {
        if (t < 31) { issue((t + 1) & 1, (t + 1) * 32); cpa_wait<1>(); }
        else        { cpa_wait<0>(); }
        __syncthreads();

        const uint32_t abase = Aa[t & 1] + (wm * 32) * (PSTR * 2) + aoff2;
        const uint32_t bbase = Ba[t & 1] + (wn * 64) * (PSTR * 2) + koff2;
        #pragma unroll
        for (int ks = 0; ks < 2; ks++) {
            uint32_t a[2][4], bb[4][4];
            #pragma unroll
            for (int mf = 0; mf < 2; mf++)
                ldsm4(a[mf][0], a[mf][1], a[mf][2], a[mf][3],
                      abase + ks * 32 + mf * 16 * PSTR * 2);
            #pragma unroll
            for (int p = 0; p < 4; p++)
                ldsm4(bb[p][0], bb[p][1], bb[p][2], bb[p][3],
                      bbase + ks * 32 + p * 16 * PSTR * 2);
            #pragma unroll
            for (int mf = 0; mf < 2; mf++)
                #pragma unroll
                for (int p = 0; p < 4; p++) {
                    mma_f16(acc[mf][2 * p],     a[mf], bb[p][0], bb[p][1]);
                    mma_f16(acc[mf][2 * p + 1], a[mf], bb[p][2], bb[p][3]);
                }
        }
        __syncthreads();
    }

    #pragma unroll
    for (int mf = 0; mf < 2; mf++) {
        int m = m0 + wm * 32 + mf * 16 + gi;
        #pragma unroll
        for (int nf = 0; nf < 8; nf++) {
            int n = n0 + wn * 64 + nf * 8 + 2 * tg;
            float b0v = bias[n], b1v = bias[n + 1];
            *(__half2*)(out + (size_t)m * DMODEL + n) =
                __floats2half2_rn((acc[mf][nf][0] + b0v) * scl, (acc[mf][nf][1] + b1v) * scl);
            *(__half2*)(out + (size_t)(m + 8) * DMODEL + n) =
                __floats2half2_rn((acc[mf][nf][2] + b0v) * scl, (acc[mf][nf][3] + b1v) * scl);
        }
    }
}

// ============================================================================
// attention, softmax over BATCH axis, fp16 HMMA m16n8k16.
// Block = (head, 64 q-rows), 256 threads = 8 warps (wq4 x wk2).
// Round-11 reg-fragment-P scheme + two latency fixes:
//  (1) k-tile 64 per barrier (two k32 sub-phases) -> HALF the barriers.
//  (2) mask prefetched into registers BEFORE each sub-phase's S MMA burst
//      -> L2 latency hidden behind tensor work instead of stalling softmax.
// smem: Q 36864 | K 2x36864 | V 2x36864 = 184320 B.
// ============================================================================
#define QB 9216u                      // 64*144: one batch of Q
#define KB 9216u                      // 64*144: one batch of K/V stage
#define KSTG 36864u                   // 4 batches
#define KOFF 36864u                   // K stages: 2 x 36864
#define VOFF 110592u                  // V stages: 2 x 36864
#define ATTN_SMEM 184320
#define NIT 32

__global__ __launch_bounds__(256, 1) void attn_kernel(const float* __restrict__ mask,
                                                      float* __restrict__ out) {
    extern __shared__ char smem[];
    const uint32_t sb = s2u(smem);
    const int tid = threadIdx.x, warp = tid >> 5, lane = tid & 31;
    const int wq = warp >> 1, wk = warp & 1;
    const int gi = lane >> 2, tg = lane & 3;
    const int mi = lane >> 3, r8 = lane & 7;
    const int qb = wq * 16, kb = wk * 16;
    const int h = blockIdx.x, q0 = blockIdx.y * 64;

    const uint32_t aoff2 = (((mi & 1) * 8 + r8) * 72 + (mi >> 1) * 8) * 2;   // A / V-trans
    const uint32_t koff2 = (((mi >> 1) * 8 + r8) * 72 + (mi & 1) * 8) * 2;   // B

    auto issue_kv = [&](int k0, int s) {
        #pragma unroll
        for (int i = 0; i < 8; i++) {
            int idx = tid + i * 256;
            int b = idx >> 9, r = (idx >> 3) & 63, ch = idx & 7;
            cpa16(sb + KOFF + s * KSTG + b * KB + r * 144u + ch * 16u,
                  g_k + ((size_t)(b * SEQ + k0 + r) << 10) + (h << 6) + (ch << 3));
        }
        #pragma unroll
        for (int i = 0; i < 8; i++) {
            int idx = tid + i * 256;
            int b = idx >> 9, r = (idx >> 3) & 63, ch = idx & 7;
            cpa16(sb + VOFF + s * KSTG + b * KB + r * 144u + ch * 16u,
                  g_v + ((size_t)(b * SEQ + k0 + r) << 10) + (h << 6) + (ch << 3));
        }
        cpa_commit();
    };

    // Prologue: Q (whole kernel) + K(0)+V(0), one group
    #pragma unroll
    for (int i = 0; i < 8; i++) {
        int idx = tid + i * 256;
        int b = idx >> 9, r = (idx >> 3) & 63, ch = idx & 7;
        cpa16(sb + b * QB + r * 144u + ch * 16u,
              g_q + ((size_t)(b * SEQ + q0 + r) << 10) + (h << 6) + (ch << 3));
    }
    issue_kv(0, 0);   // commits Q+K0+V0 together

    float O[4][8][4];
    #pragma unroll
    for (int b = 0; b < 4; b++)
        #pragma unroll
        for (int j = 0; j < 8; j++)
            #pragma unroll
            for (int c = 0; c < 4; c++) O[b][j][c] = 0.f;

    for (int t = 0; t < NIT; t++) {
        const int s = t & 1;

        cpa_wait<0>();            // own slice of group t arrived
        __syncthreads();          // everyone's slice visible; iter t-1 reads done
        if (t + 1 < NIT) issue_kv((t + 1) * 64, 1 - s);  // overlaps compute(t)

        #pragma unroll
        for (int u = 0; u < 2; u++) {         // two k32 sub-phases per tile
            const int k0 = t * 64 + u * 32;
            const uint32_t krow = u * 32u;

            // ---- mask prefetch (issues LDGs; drains behind the S MMA burst)
            float2 mv[2][2][4];
            #pragma unroll
            for (int nf = 0; nf < 2; nf++)
                #pragma unroll
                for (int half = 0; half < 2; half++) {
                    const int ql = qb + gi + half * 8;
                    const int klo = kb + nf * 8 + 2 * tg;
                    const float* mptr = mask + (size_t)(q0 + ql) * SEQ + k0 + klo;
                    #pragma unroll
                    for (int b = 0; b < 4; b++)
                        mv[nf][half][b] = *(const float2*)(mptr + (size_t)b * SEQ * SEQ);
                }

            // ---- S = Q K^T : warp slice q16 x k16 (stage s, sub-phase u) ----
            float S[4][2][4];
            #pragma unroll
            for (int b = 0; b < 4; b++)
                #pragma unroll
                for (int nf = 0; nf < 2; nf++)
                    #pragma unroll
                    for (int c = 0; c < 4; c++) S[b][nf][c] = 0.f;

            #pragma unroll
            for (int b = 0; b < 4; b++) {
                const uint32_t qbase = sb + b * QB + qb * 144u + aoff2;
                const uint32_t kbase = sb + KOFF + s * KSTG + b * KB + (krow + kb) * 144u + koff2;
                #pragma unroll
                for (int ds = 0; ds < 4; ds++) {
                    uint32_t a[4], b0, b1, b2, b3;
                    ldsm4(a[0], a[1], a[2], a[3], qbase + ds * 32);
                    ldsm4(b0, b1, b2, b3, kbase + ds * 32);
                    mma_f16(S[b][0], a, b0, b1);
                    mma_f16(S[b][1], a, b2, b3);
                }
            }

            // ---- softmax across batch (thread-local), P packed into A-frag regs
            uint32_t P[4][4];
            #pragma unroll
            for (int nf = 0; nf < 2; nf++) {
                #pragma unroll
                for (int half = 0; half < 2; half++) {
                    float p0[4], p1[4];
                    #pragma unroll
                    for (int j = 0; j < 2; j++) {
                        float z[4];
                        #pragma unroll
                        for (int b = 0; b < 4; b++) {
                            float mm = j ? mv[nf][half][b].y : mv[nf][half][b].x;
                            z[b] = __fadd_rn(S[b][nf][half * 2 + j], __fmul_rn(mm, -1e9f));
                        }
                        float mx = fmaxf(fmaxf(z[0], z[1]), fmaxf(z[2], z[3]));
                        float e0 = __expf(z[0] - mx), e1 = __expf(z[1] - mx);
                        float e2 = __expf(z[2] - mx), e3 = __expf(z[3] - mx);
                        float inv = __fdividef(1.0f, (e0 + e1) + (e2 + e3));
                        if (j == 0) { p0[0] = e0 * inv; p0[1] = e1 * inv; p0[2] = e2 * inv; p0[3] = e3 * inv; }
                        else        { p1[0] = e0 * inv; p1[1] = e1 * inv; p1[2] = e2 * inv; p1[3] = e3 * inv; }
                    }
                    #pragma unroll
                    for (int b = 0; b < 4; b++)
                        P[b][nf * 2 + half] = pack_f16x2(p0[b], p1[b]);
                }
            }

            // ---- O += P V : partial over this warp's k16, ALL d64 ----
            #pragma unroll
            for (int b = 0; b < 4; b++) {
                const uint32_t vbase = sb + VOFF + s * KSTG + b * KB + (krow + kb) * 144u + aoff2;
                #pragma unroll
                for (int j = 0; j < 4; j++) {       // d-groups of 16
                    uint32_t v0, v1, v2, v3;
                    ldsm4t(v0, v1, v2, v3, vbase + j * 32u);
                    mma_f16(O[b][j * 2],     P[b], v0, v1);
                    mma_f16(O[b][j * 2 + 1], P[b], v2, v3);
                }
            }
        }
    }

    // ---- epilogue: sum the two k-warp partials via smem, then store ----
    __syncthreads();                 // all PV reads done; smem reusable
    float* ex = (float*)smem;        // 4 wq-warps x 4096 floats = 64KB
    if (wk == 1) {
        #pragma unroll
        for (int b = 0; b < 4; b++)
            #pragma unroll
            for (int j = 0; j < 8; j++) {
                int idx = b * 8 + j;
                *(float4*)&ex[wq * 4096 + idx * 128 + lane * 4] =
                    make_float4(O[b][j][0], O[b][j][1], O[b][j][2], O[b][j][3]);
            }
    }
    __syncthreads();
    if (wk == 0) {
        #pragma unroll
        for (int b = 0; b < 4; b++)
            #pragma unroll
            for (int j = 0; j < 8; j++) {
                int idx = b * 8 + j;
                float4 v = *(const float4*)&ex[wq * 4096 + idx * 128 + lane * 4];
                O[b][j][0] += v.x; O[b][j][1] += v.y; O[b][j][2] += v.z; O[b][j][3] += v.w;
            }
        #pragma unroll
        for (int b = 0; b < 4; b++) {
            #pragma unroll
            for (int j = 0; j < 8; j++) {
                int dg = (h << 6) + j * 8 + 2 * tg;
                int qg = q0 + qb + gi;
                *(float2*)(out + ((size_t)b * SEQ + qg) * DMODEL + dg) =
                    make_float2(O[b][j][0], O[b][j][1]);
                *(float2*)(out + ((size_t)b * SEQ + qg + 8) * DMODEL + dg) =
                    make_float2(O[b][j][2], O[b][j][3]);
            }
        }
    }
}

// ============================================================================
extern "C" void kernel_launch(void* const* d_in, const int* in_sizes, int n_in,
                              void* d_out, int out_size) {
    (void)in_sizes; (void)n_in; (void)out_size;
    const float* xq   = (const float*)d_in[0];
    const float* xk   = (const float*)d_in[1];
    const float* xv   = (const float*)d_in[2];
    const float* mask = (const float*)d_in[3];
    const float* Wq   = (const float*)d_in[4];
    const float* bq   = (const float*)d_in[5];
    const float* Wk   = (const float*)d_in[6];
    const float* bk   = (const float*)d_in[7];
    const float* Wv   = (const float*)d_in[8];
    const float* bv   = (const float*)d_in[9];
    float* out = (float*)d_out;

    cudaFuncSetAttribute(attn_kernel, cudaFuncAttributeMaxDynamicSharedMemorySize, ATTN_SMEM);

    round_x_kernel<<<dim3(8192, 3), 256>>>((const float4*)xq, (const float4*)xk, (const float4*)xv);
    wtrans_kernel<<<dim3(16, 16, 3), 256>>>(Wq, Wk, Wv);
    proj_kernel<<<dim3(DMODEL / 128, (NB * SEQ) / 128, 3), 256>>>(bq, bk, bv);
    attn_kernel<<<dim3(NH, SEQ / 64), 256, ATTN_SMEM>>>(mask, out);
}

// round 13
// speedup vs baseline: 1.4280x; 1.4280x over previous
#include <cuda_runtime.h>
#include <cuda_fp16.h>
#include <cstdint>
#include <cstddef>

#define NB 4
#define SEQ 2048
#define NH 16
#define HD 64
#define DMODEL 1024

// Scratch (allocation-free rule -> __device__ globals), all fp16
__device__ __half g_x[3u * 8192u * 1024u];   // rounded inputs
__device__ __half g_wt[3u * 1024u * 1024u];  // W transposed [n][k]
__device__ __half g_q[NB * SEQ * DMODEL];    // Q pre-scaled by 0.125
__device__ __half g_k[NB * SEQ * DMODEL];
__device__ __half g_v[NB * SEQ * DMODEL];

// ---------------------------------------------------------------------------
__device__ __forceinline__ uint32_t s2u(const void* p) {
    return (uint32_t)__cvta_generic_to_shared(p);
}
__device__ __forceinline__ void ldsm4(uint32_t& r0, uint32_t& r1, uint32_t& r2, uint32_t& r3,
                                      uint32_t addr) {
    asm volatile("ldmatrix.sync.aligned.m8n8.x4.shared.b16 {%0,%1,%2,%3}, [%4];"
                 : "=r"(r0), "=r"(r1), "=r"(r2), "=r"(r3) : "r"(addr));
}
__device__ __forceinline__ void ldsm4t(uint32_t& r0, uint32_t& r1, uint32_t& r2, uint32_t& r3,
                                       uint32_t addr) {
    asm volatile("ldmatrix.sync.aligned.m8n8.x4.trans.shared.b16 {%0,%1,%2,%3}, [%4];"
                 : "=r"(r0), "=r"(r1), "=r"(r2), "=r"(r3) : "r"(addr));
}
__device__ __forceinline__ void cpa16(uint32_t dst, const void* src) {
    asm volatile("cp.async.cg.shared.global [%0], [%1], 16;" :: "r"(dst), "l"(src));
}
__device__ __forceinline__ void cpa_commit() { asm volatile("cp.async.commit_group;"); }
template <int N> __device__ __forceinline__ void cpa_wait() {
    asm volatile("cp.async.wait_group %0;" :: "n"(N));
}
// pack two fp32 -> one f16x2 register (round-to-nearest-even, == __float2half_rn x2)
__device__ __forceinline__ uint32_t pack_f16x2(float lo, float hi) {
    uint32_t r;
    asm("cvt.rn.f16x2.f32 %0, %1, %2;" : "=r"(r) : "f"(hi), "f"(lo));
    return r;
}
// fp16 inputs, fp32 accumulate: same significand width as tf32, 2x rate, K=16
__device__ __forceinline__ void mma_f16(float c[4], const uint32_t a[4], uint32_t b0, uint32_t b1) {
    asm volatile(
        "mma.sync.aligned.m16n8k16.row.col.f32.f16.f16.f32 "
        "{%0,%1,%2,%3}, {%4,%5,%6,%7}, {%8,%9}, {%0,%1,%2,%3};\n"
        : "+f"(c[0]), "+f"(c[1]), "+f"(c[2]), "+f"(c[3])
        : "r"(a[0]), "r"(a[1]), "r"(a[2]), "r"(a[3]), "r"(b0), "r"(b1));
}

// ============================================================================
// prep 1: round X inputs to fp16
// ============================================================================
__global__ void round_x_kernel(const float4* __restrict__ xq,
                               const float4* __restrict__ xk,
                               const float4* __restrict__ xv) {
    const int z = blockIdx.y;
    const float4* src = (z == 0) ? xq : (z == 1) ? xk : xv;
    __half2* dst = (__half2*)(g_x + (size_t)z * 8388608u);
    size_t i = (size_t)blockIdx.x * blockDim.x + threadIdx.x;
    float4 v = src[i];
    dst[2 * i]     = __floats2half2_rn(v.x, v.y);
    dst[2 * i + 1] = __floats2half2_rn(v.z, v.w);
}

// ============================================================================
// prep 2: transpose + round W -> g_wt[z][n][k] fp16
// ============================================================================
__global__ void wtrans_kernel(const float* __restrict__ Wq,
                              const float* __restrict__ Wk,
                              const float* __restrict__ Wv) {
    __shared__ float smw[64][68];
    const int z = blockIdx.z;
    const float* W = (z == 0) ? Wq : (z == 1) ? Wk : Wv;
    __half* Wt = g_wt + (size_t)z * 1048576u;
    const int k0 = blockIdx.y * 64, n0 = blockIdx.x * 64;
    const int tid = threadIdx.x;
    #pragma unroll
    for (int i = 0; i < 4; i++) {
        int idx = tid + i * 256, r = idx >> 4, c4 = idx & 15;
        float4 v = *(const float4*)(W + (size_t)(k0 + r) * 1024 + n0 + c4 * 4);
        *(float4*)&smw[r][c4 * 4] = v;
    }
    __syncthreads();
    #pragma unroll
    for (int i = 0; i < 4; i++) {
        int idx = tid + i * 256, n = idx >> 4, c4 = idx & 15;
        __half* o = Wt + (size_t)(n0 + n) * 1024 + k0 + c4 * 4;
        *(__half2*)(o)     = __floats2half2_rn(smw[c4 * 4 + 0][n], smw[c4 * 4 + 1][n]);
        *(__half2*)(o + 2) = __floats2half2_rn(smw[c4 * 4 + 2][n], smw[c4 * 4 + 3][n]);
    }
}

// ============================================================================
// projections: X(fp16) @ W(fp16) + b, fp32 accum, out fp16.
// Block 128x128, BK=32, cp.async double-buffered, 256 threads (4m x 2n warps).
// ============================================================================
#define PSTR 40
__global__ __launch_bounds__(256, 2) void proj_kernel(
    const float* __restrict__ bq, const float* __restrict__ bk, const float* __restrict__ bv) {
    __shared__ __half As[2][128 * PSTR];
    __shared__ __half Bs[2][128 * PSTR];

    const int z = blockIdx.z;
    const __half* X  = g_x  + (size_t)z * 8388608u;
    const __half* Wt = g_wt + (size_t)z * 1048576u;
    const float* bias = (z == 0) ? bq : (z == 1) ? bk : bv;
    __half* out = (z == 0) ? g_q : (z == 1) ? g_k : g_v;
    const float scl = (z == 0) ? 0.125f : 1.0f;

    const int m0 = blockIdx.y * 128, n0 = blockIdx.x * 128;
    const int tid = threadIdx.x, warp = tid >> 5, lane = tid & 31;
    const int wm = warp >> 1, wn = warp & 1;
    const int gi = lane >> 2, tg = lane & 3;
    const int mi = lane >> 3, r8 = lane & 7;
    const uint32_t aoff2 = (((mi & 1) * 8 + r8) * PSTR + (mi >> 1) * 8) * 2;
    const uint32_t koff2 = (((mi >> 1) * 8 + r8) * PSTR + (mi & 1) * 8) * 2;
    const uint32_t Aa[2] = { s2u(As[0]), s2u(As[1]) };
    const uint32_t Ba[2] = { s2u(Bs[0]), s2u(Bs[1]) };

    auto issue = [&](int s, int kk) {
        #pragma unroll
        for (int i = 0; i < 2; i++) {
            int idx = tid + i * 256, r = idx >> 2, c8 = idx & 3;
            cpa16(Aa[s] + r * (PSTR * 2) + c8 * 16, X + (size_t)(m0 + r) * 1024 + kk + c8 * 8);
        }
        #pragma unroll
        for (int i = 0; i < 2; i++) {
            int idx = tid + i * 256, n = idx >> 2, c8 = idx & 3;
            cpa16(Ba[s] + n * (PSTR * 2) + c8 * 16, Wt + (size_t)(n0 + n) * 1024 + kk + c8 * 8);
        }
        cpa_commit();
    };

    float acc[2][8][4];
    #pragma unroll
    for (int i = 0; i < 2; i++)
        #pragma unroll
        for (int j = 0; j < 8; j++)
            #pragma unroll
            for (int c = 0; c < 4; c++) acc[i][j][c] = 0.f;

    issue(0, 0);
    for (int t = 0; t < 32; t++) {
        if (t < 31) { issue((t + 1) & 1, (t + 1) * 32); cpa_wait<1>(); }
        else        { cpa_wait<0>(); }
        __syncthreads();

        const uint32_t abase = Aa[t & 1] + (wm * 32) * (PSTR * 2) + aoff2;
        const uint32_t bbase = Ba[t & 1] + (wn * 64) * (PSTR * 2) + koff2;
        #pragma unroll
        for (int ks = 0; ks < 2; ks++) {
            uint32_t a[2][4], bb[4][4];
            #pragma unroll
            for (int mf = 0; mf < 2; mf++)
                ldsm4(a[mf][0], a[mf][1], a[mf][2], a[mf][3],
                      abase + ks * 32 + mf * 16 * PSTR * 2);
            #pragma unroll
            for (int p = 0; p < 4; p++)
                ldsm4(bb[p][0], bb[p][1], bb[p][2], bb[p][3],
                      bbase + ks * 32 + p * 16 * PSTR * 2);
            #pragma unroll
            for (int mf = 0; mf < 2; mf++)
                #pragma unroll
                for (int p = 0; p < 4; p++) {
                    mma_f16(acc[mf][2 * p],     a[mf], bb[p][0], bb[p][1]);
                    mma_f16(acc[mf][2 * p + 1], a[mf], bb[p][2], bb[p][3]);
                }
        }
        __syncthreads();
    }

    #pragma unroll
    for (int mf = 0; mf < 2; mf++) {
        int m = m0 + wm * 32 + mf * 16 + gi;
        #pragma unroll
        for (int nf = 0; nf < 8; nf++) {
            int n = n0 + wn * 64 + nf * 8 + 2 * tg;
            float b0v = bias[n], b1v = bias[n + 1];
            *(__half2*)(out + (size_t)m * DMODEL + n) =
                __floats2half2_rn((acc[mf][nf][0] + b0v) * scl, (acc[mf][nf][1] + b1v) * scl);
            *(__half2*)(out + (size_t)(m + 8) * DMODEL + n) =
                __floats2half2_rn((acc[mf][nf][2] + b0v) * scl, (acc[mf][nf][3] + b1v) * scl);
        }
    }
}

// ============================================================================
// attention, softmax over BATCH axis, fp16 HMMA m16n8k16.
// Round-11 structure (best known: reg-fragment P, one barrier/iter, k-tile 32)
// + register-neutral mask fix: mask tile streamed into SMEM via cp.async,
// double-buffered one iteration ahead (same commit group as K/V). Softmax
// reads mask via LDS (29cyc, prefetched) instead of cold ~600cyc DRAM LDG.
// smem: Q 36864 | K 2x18432 | V 2x18432 | mask 2x36864 = 184320 B.
// Mask tile layout: [b][q64][k32] fp32, row stride 144B (bank-spread).
// ============================================================================
#define QB 9216u                      // 64*144: one batch of Q
#define KB 4608u                      // 32*144: one batch of K/V stage
#define KSTG 18432u                   // 4 batches
#define KOFF 36864u                   // K stages: 2 x 18432
#define VOFF 73728u                   // V stages: 2 x 18432
#define MOFF 110592u                  // mask stages: 2 x 36864
#define MSTG 36864u                   // 4b x 64q x 144B
#define MB 9216u                      // one batch of mask tile (64 x 144B)
#define ATTN_SMEM 184320
#define NIT 64

__global__ __launch_bounds__(256, 1) void attn_kernel(const float* __restrict__ mask,
                                                      float* __restrict__ out) {
    extern __shared__ char smem[];
    const uint32_t sb = s2u(smem);
    const int tid = threadIdx.x, warp = tid >> 5, lane = tid & 31;
    const int wq = warp >> 1, wk = warp & 1;
    const int gi = lane >> 2, tg = lane & 3;
    const int mi = lane >> 3, r8 = lane & 7;
    const int qb = wq * 16, kb = wk * 16;
    const int h = blockIdx.x, q0 = blockIdx.y * 64;

    const uint32_t aoff2 = (((mi & 1) * 8 + r8) * 72 + (mi >> 1) * 8) * 2;   // A / V-trans
    const uint32_t koff2 = (((mi >> 1) * 8 + r8) * 72 + (mi & 1) * 8) * 2;   // B

    auto issue_kv = [&](int k0, int s) {
        #pragma unroll
        for (int i = 0; i < 4; i++) {
            int idx = tid + i * 256;
            int b = idx >> 8, r = (idx >> 3) & 31, ch = idx & 7;
            cpa16(sb + KOFF + s * KSTG + b * KB + r * 144u + ch * 16u,
                  g_k + ((size_t)(b * SEQ + k0 + r) << 10) + (h << 6) + (ch << 3));
        }
        #pragma unroll
        for (int i = 0; i < 4; i++) {
            int idx = tid + i * 256;
            int b = idx >> 8, r = (idx >> 3) & 31, ch = idx & 7;
            cpa16(sb + VOFF + s * KSTG + b * KB + r * 144u + ch * 16u,
                  g_v + ((size_t)(b * SEQ + k0 + r) << 10) + (h << 6) + (ch << 3));
        }
        // mask tile: 4b x 64q x 32k fp32 = 128B per (b,row), 8 x 16B chunks
        #pragma unroll
        for (int i = 0; i < 8; i++) {
            int idx = tid + i * 256;
            int b = idx >> 9, r = (idx >> 3) & 63, ch = idx & 7;
            cpa16(sb + MOFF + s * MSTG + b * MB + r * 144u + ch * 16u,
                  mask + (size_t)b * SEQ * SEQ + (size_t)(q0 + r) * SEQ + k0 + ch * 4);
        }
        cpa_commit();
    };

    // Prologue: Q (whole kernel) + K(0)+V(0)+mask(0), one group
    #pragma unroll
    for (int i = 0; i < 8; i++) {
        int idx = tid + i * 256;
        int b = idx >> 9, r = (idx >> 3) & 63, ch = idx & 7;
        cpa16(sb + b * QB + r * 144u + ch * 16u,
              g_q + ((size_t)(b * SEQ + q0 + r) << 10) + (h << 6) + (ch << 3));
    }
    issue_kv(0, 0);   // commits Q+K0+V0+M0 together

    float O[4][8][4];
    #pragma unroll
    for (int b = 0; b < 4; b++)
        #pragma unroll
        for (int j = 0; j < 8; j++)
            #pragma unroll
            for (int c = 0; c < 4; c++) O[b][j][c] = 0.f;

    for (int t = 0; t < NIT; t++) {
        const int s = t & 1;

        cpa_wait<0>();            // own slice of group t arrived
        __syncthreads();          // everyone's slice visible; iter t-1 reads done
        if (t + 1 < NIT) issue_kv((t + 1) * 32, 1 - s);  // overlaps compute(t)

        // ---- S = Q K^T : warp slice q16 x k16 (stage s) ----
        float S[4][2][4];
        #pragma unroll
        for (int b = 0; b < 4; b++)
            #pragma unroll
            for (int nf = 0; nf < 2; nf++)
                #pragma unroll
                for (int c = 0; c < 4; c++) S[b][nf][c] = 0.f;

        #pragma unroll
        for (int b = 0; b < 4; b++) {
            const uint32_t qbase = sb + b * QB + qb * 144u + aoff2;
            const uint32_t kbase = sb + KOFF + s * KSTG + b * KB + kb * 144u + koff2;
            #pragma unroll
            for (int ds = 0; ds < 4; ds++) {
                uint32_t a[4], b0, b1, b2, b3;
                ldsm4(a[0], a[1], a[2], a[3], qbase + ds * 32);
                ldsm4(b0, b1, b2, b3, kbase + ds * 32);
                mma_f16(S[b][0], a, b0, b1);
                mma_f16(S[b][1], a, b2, b3);
            }
        }

        // ---- softmax across batch (thread-local), mask from SMEM (prefetched),
        //      P packed straight into fp16 A-fragment registers ----
        uint32_t P[4][4];
        #pragma unroll
        for (int nf = 0; nf < 2; nf++) {
            #pragma unroll
            for (int half = 0; half < 2; half++) {
                const int ql = qb + gi + half * 8;
                const int klo = kb + nf * 8 + 2 * tg;
                const char* mrow = smem + MOFF + s * MSTG + ql * 144u + klo * 4u;
                float2 mv[4];
                #pragma unroll
                for (int b = 0; b < 4; b++)
                    mv[b] = *(const float2*)(mrow + b * MB);
                float p0[4], p1[4];
                #pragma unroll
                for (int j = 0; j < 2; j++) {
                    float z[4];
                    #pragma unroll
                    for (int b = 0; b < 4; b++) {
                        float mm = j ? mv[b].y : mv[b].x;
                        z[b] = __fadd_rn(S[b][nf][half * 2 + j], __fmul_rn(mm, -1e9f));
                    }
                    float mx = fmaxf(fmaxf(z[0], z[1]), fmaxf(z[2], z[3]));
                    float e0 = __expf(z[0] - mx), e1 = __expf(z[1] - mx);
                    float e2 = __expf(z[2] - mx), e3 = __expf(z[3] - mx);
                    float inv = __fdividef(1.0f, (e0 + e1) + (e2 + e3));
                    if (j == 0) { p0[0] = e0 * inv; p0[1] = e1 * inv; p0[2] = e2 * inv; p0[3] = e3 * inv; }
                    else        { p1[0] = e0 * inv; p1[1] = e1 * inv; p1[2] = e2 * inv; p1[3] = e3 * inv; }
                }
                #pragma unroll
                for (int b = 0; b < 4; b++)
                    P[b][nf * 2 + half] = pack_f16x2(p0[b], p1[b]);
            }
        }

        // ---- O += P V : partial over this warp's k16, ALL d64 ----
        #pragma unroll
        for (int b = 0; b < 4; b++) {
            const uint32_t vbase = sb + VOFF + s * KSTG + b * KB + kb * 144u + aoff2;
            #pragma unroll
            for (int j = 0; j < 4; j++) {       // d-groups of 16
                uint32_t v0, v1, v2, v3;
                ldsm4t(v0, v1, v2, v3, vbase + j * 32u);
                mma_f16(O[b][j * 2],     P[b], v0, v1);
                mma_f16(O[b][j * 2 + 1], P[b], v2, v3);
            }
        }
    }

    // ---- epilogue: sum the two k-warp partials via smem, then store ----
    __syncthreads();                 // all PV reads done; smem reusable
    float* ex = (float*)smem;        // 4 wq-warps x 4096 floats = 64KB
    if (wk == 1) {
        #pragma unroll
        for (int b = 0; b < 4; b++)
            #pragma unroll
            for (int j = 0; j < 8; j++) {
                int idx = b * 8 + j;
                *(float4*)&ex[wq * 4096 + idx * 128 + lane * 4] =
                    make_float4(O[b][j][0], O[b][j][1], O[b][j][2], O[b][j][3]);
            }
    }
    __syncthreads();
    if (wk == 0) {
        #pragma unroll
        for (int b = 0; b < 4; b++)
            #pragma unroll
            for (int j = 0; j < 8; j++) {
                int idx = b * 8 + j;
                float4 v = *(const float4*)&ex[wq * 4096 + idx * 128 + lane * 4];
                O[b][j][0] += v.x; O[b][j][1] += v.y; O[b][j][2] += v.z; O[b][j][3] += v.w;
            }
        #pragma unroll
        for (int b = 0; b < 4; b++) {
            #pragma unroll
            for (int j = 0; j < 8; j++) {
                int dg = (h << 6) + j * 8 + 2 * tg;
                int qg = q0 + qb + gi;
                *(float2*)(out + ((size_t)b * SEQ + qg) * DMODEL + dg) =
                    make_float2(O[b][j][0], O[b][j][1]);
                *(float2*)(out + ((size_t)b * SEQ + qg + 8) * DMODEL + dg) =
                    make_float2(O[b][j][2], O[b][j][3]);
            }
        }
    }
}

// ============================================================================
extern "C" void kernel_launch(void* const* d_in, const int* in_sizes, int n_in,
                              void* d_out, int out_size) {
    (void)in_sizes; (void)n_in; (void)out_size;
    const float* xq   = (const float*)d_in[0];
    const float* xk   = (const float*)d_in[1];
    const float* xv   = (const float*)d_in[2];
    const float* mask = (const float*)d_in[3];
    const float* Wq   = (const float*)d_in[4];
    const float* bq   = (const float*)d_in[5];
    const float* Wk   = (const float*)d_in[6];
    const float* bk   = (const float*)d_in[7];
    const float* Wv   = (const float*)d_in[8];
    const float* bv   = (const float*)d_in[9];
    float* out = (float*)d_out;

    cudaFuncSetAttribute(attn_kernel, cudaFuncAttributeMaxDynamicSharedMemorySize, ATTN_SMEM);

    round_x_kernel<<<dim3(8192, 3), 256>>>((const float4*)xq, (const float4*)xk, (const float4*)xv);
    wtrans_kernel<<<dim3(16, 16, 3), 256>>>(Wq, Wk, Wv);
    proj_kernel<<<dim3(DMODEL / 128, (NB * SEQ) / 128, 3), 256>>>(bq, bk, bv);
    attn_kernel<<<dim3(NH, SEQ / 64), 256, ATTN_SMEM>>>(mask, out);
}